// round 1
// baseline (speedup 1.0000x reference)
#include <cuda_runtime.h>

// ---------------------------------------------------------------------------
// CaT: 4-layer DAG-masked transformer, fp32.
// B=16, N=512, D=256, H=8, HS=64, FF=1024, L=4.
// Row index r = b*512 + n  (BN = 8192 rows).
// Q/K/V stored "n-major": buf[n*8192 + b*512 + h*64 + hs]  (512 x 8192)
// so that A @ Q / A @ V is a single GEMM with the shared (512x512) mask A.
// ---------------------------------------------------------------------------

#define DI __device__ __forceinline__

static DI float swishf(float x) { return x / (1.f + __expf(-x)); }

// ------------------------- static device scratch ---------------------------
__device__ float g_Wpack[4 * 256 * 1536];      // packed [l][d][ (t,h,hs) ]
__device__ float g_Bias [4 * 1536];
__device__ unsigned char g_Amask[2 * 512 * 512]; // [v][i*512+j], v=0 layer0, v=1 layers 1..3
__device__ float g_Qn[512 * 8192];
__device__ float g_Kn[512 * 8192];
__device__ float g_Vn[512 * 8192];
__device__ float g_AQ[512 * 8192];
__device__ float g_AV[512 * 8192];
__device__ float g_Tb[33554432];               // 128 * 512 * 512 scores/probs
__device__ float g_Ob[8192 * 512];
__device__ float g_Mha[8192 * 256];
__device__ float g_Ff [8192 * 1024];
__device__ float g_Xb [8192 * 256];

// ------------------------------ prep kernels -------------------------------
__global__ void pack_w_k(const float* __restrict__ Wk, const float* __restrict__ Wq,
                         const float* __restrict__ Wv, const float* __restrict__ bk,
                         const float* __restrict__ bq, const float* __restrict__ bv) {
    int idx = blockIdx.x * 256 + threadIdx.x;
    if (idx < 4 * 256 * 1536) {
        int l = idx / (256 * 1536);
        int rem = idx - l * (256 * 1536);
        int d = rem / 1536;
        int c = rem - d * 1536;
        int t = c >> 9, h = (c >> 6) & 7, hs = c & 63;
        const float* W = (t == 0) ? Wk : (t == 1) ? Wq : Wv;
        g_Wpack[idx] = W[(((size_t)(l * 8 + h)) * 256 + d) * 64 + hs];
    }
    if (idx < 4 * 1536) {
        int l = idx / 1536;
        int c = idx - l * 1536;
        int t = c >> 9, h = (c >> 6) & 7, hs = c & 63;
        const float* bb = (t == 0) ? bk : (t == 1) ? bq : bv;
        g_Bias[idx] = bb[(l * 8 + h) * 64 + hs];
    }
}

__global__ void mask_k(const int* __restrict__ dag) {
    int idx = blockIdx.x * 256 + threadIdx.x;       // < 524288
    int v = idx >> 18;
    int rem = idx & 262143;
    int i = rem >> 9;
    int j = rem & 511;
    // A = d.T : A[i][j] = clip(dag + (v? I : 0))[j][i]
    g_Amask[idx] = (unsigned char)((dag[j * 512 + i] != 0 || (v && i == j)) ? 1 : 0);
}

// ------------------------------- GEMM core ---------------------------------
struct GemmParams {
    const void*  A = nullptr;
    const float* B = nullptr;
    float*       C = nullptr;
    const float* bias = nullptr;
    const float* res  = nullptr;
    const unsigned char* mask = nullptr;
    float* dst0 = nullptr;   // K buffer (mode 1)
    float* dst1 = nullptr;   // Q buffer
    float* dst2 = nullptr;   // V buffer
    int K = 0, lda = 0, ldb = 0, ldc = 0;
    long long sAz = 0, sBz = 0, sCz = 0;
};

// MODE: 0 plain, 1 QKV scatter+swish, 2 scale+mask, 3 PV(+AV scatter),
//       4 bias+swish, 5 bias+residual, 6 bias
template <int BM, int BN, int BK, bool TRANSB, bool AU8, int MODE>
__global__ __launch_bounds__(256, 1) void gemm_k(GemmParams p) {
    constexpr int RB = BM / 64;
    constexpr int CB = BN / 64;
    __shared__ float As[BK][BM];
    __shared__ float Bs[BK][BN];

    const int t  = threadIdx.x;
    const int bx = blockIdx.x, by = blockIdx.y, bz = blockIdx.z;

    const float* B = p.B + (size_t)bz * p.sBz;
    float*       C = p.C + (size_t)bz * p.sCz;
    const unsigned char* A8 = nullptr;
    const float*         Af = nullptr;
    if (AU8) A8 = (const unsigned char*)p.A + (size_t)bz * p.sAz + (size_t)by * BM * p.lda;
    else     Af = (const float*)p.A + (size_t)bz * p.sAz + (size_t)by * BM * p.lda;

    float acc[RB][CB][4][4];
#pragma unroll
    for (int rb = 0; rb < RB; rb++)
#pragma unroll
        for (int cb = 0; cb < CB; cb++)
#pragma unroll
            for (int i = 0; i < 4; i++)
#pragma unroll
                for (int j = 0; j < 4; j++) acc[rb][cb][i][j] = 0.f;

    const int ar = t >> 1, ak = (t & 1) << 2;   // A tile: 128 rows x 8 k
    const int tx = t & 15, ty = t >> 4;

    for (int k0 = 0; k0 < p.K; k0 += BK) {
        if (AU8) {
            unsigned int w = *(const unsigned int*)(A8 + (size_t)ar * p.lda + k0 + ak);
            As[ak + 0][ar] = (float)(w & 255u);
            As[ak + 1][ar] = (float)((w >> 8) & 255u);
            As[ak + 2][ar] = (float)((w >> 16) & 255u);
            As[ak + 3][ar] = (float)(w >> 24);
        } else {
            const float4 v = *(const float4*)(Af + (size_t)ar * p.lda + k0 + ak);
            As[ak + 0][ar] = v.x; As[ak + 1][ar] = v.y;
            As[ak + 2][ar] = v.z; As[ak + 3][ar] = v.w;
        }
        if (TRANSB) {
            const int bn = t >> 1, bk = (t & 1) << 2;
            const float4 v = *(const float4*)(B + (size_t)(bx * BN + bn) * p.ldb + k0 + bk);
            Bs[bk + 0][bn] = v.x; Bs[bk + 1][bn] = v.y;
            Bs[bk + 2][bn] = v.z; Bs[bk + 3][bn] = v.w;
        } else if (BK * BN >= 1024) {
            const int br = t >> 5, bc = (t & 31) << 2;
            *(float4*)&Bs[br][bc] =
                *(const float4*)(B + (size_t)(k0 + br) * p.ldb + bx * BN + bc);
        } else {
            if (t < 128) {
                const int br = t >> 4, bc = (t & 15) << 2;
                *(float4*)&Bs[br][bc] =
                    *(const float4*)(B + (size_t)(k0 + br) * p.ldb + bx * BN + bc);
            }
        }
        __syncthreads();

#pragma unroll
        for (int kk = 0; kk < BK; kk++) {
            float a[RB][4], b[CB][4];
#pragma unroll
            for (int rb = 0; rb < RB; rb++)
                *(float4*)a[rb] = *(const float4*)&As[kk][rb * 64 + ty * 4];
#pragma unroll
            for (int cb = 0; cb < CB; cb++)
                *(float4*)b[cb] = *(const float4*)&Bs[kk][cb * 64 + tx * 4];
#pragma unroll
            for (int rb = 0; rb < RB; rb++)
#pragma unroll
                for (int cb = 0; cb < CB; cb++)
#pragma unroll
                    for (int i = 0; i < 4; i++)
#pragma unroll
                        for (int j = 0; j < 4; j++)
                            acc[rb][cb][i][j] = fmaf(a[rb][i], b[cb][j], acc[rb][cb][i][j]);
        }
        __syncthreads();
    }

    // epilogue
#pragma unroll
    for (int rb = 0; rb < RB; rb++)
#pragma unroll
        for (int i = 0; i < 4; i++) {
            const int gm = by * BM + rb * 64 + ty * 4 + i;
#pragma unroll
            for (int cb = 0; cb < CB; cb++)
#pragma unroll
                for (int j = 0; j < 4; j++) {
                    const int gn = bx * BN + cb * 64 + tx * 4 + j;
                    float v = acc[rb][cb][i][j];
                    if (MODE == 0) {
                        C[(size_t)gm * p.ldc + gn] = v;
                    } else if (MODE == 1) {
                        v = swishf(v + p.bias[gn]);
                        const int tt = gn >> 9, h = (gn >> 6) & 7, hs = gn & 63;
                        const int b = gm >> 9, n = gm & 511;
                        float* d = (tt == 0) ? p.dst0 : (tt == 1) ? p.dst1 : p.dst2;
                        d[(size_t)n * 8192 + b * 512 + h * 64 + hs] = v;
                    } else if (MODE == 2) {
                        v = p.mask[gm * 512 + gn] ? v * 0.125f : -3.0e38f;
                        C[(size_t)gm * p.ldc + gn] = v;
                    } else if (MODE == 3) {
                        v += p.res[(size_t)gm * 8192 + bz * 64 + gn];
                        C[(size_t)((bz >> 3) * 512 + gm) * 512 + (bz & 7) * 64 + gn] = v;
                    } else if (MODE == 4) {
                        C[(size_t)gm * p.ldc + gn] = swishf(v + p.bias[gn]);
                    } else if (MODE == 5) {
                        C[(size_t)gm * p.ldc + gn] =
                            v + p.bias[gn] + p.res[(size_t)gm * p.ldc + gn];
                    } else {
                        C[(size_t)gm * p.ldc + gn] = v + p.bias[gn];
                    }
                }
        }
}

// ------------------------------- softmax -----------------------------------
__global__ void softmax_k(float* __restrict__ T) {
    int row  = blockIdx.x * 8 + (threadIdx.x >> 5);   // 65536 rows total
    int lane = threadIdx.x & 31;
    float* r = T + (size_t)row * 512;
    float x[16];
    float m = -3.4e38f;
#pragma unroll
    for (int k = 0; k < 16; k++) { x[k] = r[k * 32 + lane]; m = fmaxf(m, x[k]); }
#pragma unroll
    for (int o = 16; o; o >>= 1) m = fmaxf(m, __shfl_xor_sync(0xffffffffu, m, o));
    if (m <= -1e37f) {  // fully-masked ("dead") row -> zeros, matching reference
#pragma unroll
        for (int k = 0; k < 16; k++) r[k * 32 + lane] = 0.f;
        return;
    }
    float s = 0.f;
#pragma unroll
    for (int k = 0; k < 16; k++) { x[k] = __expf(x[k] - m); s += x[k]; }
#pragma unroll
    for (int o = 16; o; o >>= 1) s += __shfl_xor_sync(0xffffffffu, s, o);
    float inv = 1.f / s;
#pragma unroll
    for (int k = 0; k < 16; k++) r[k * 32 + lane] = x[k] * inv;
}

// ------------------------------ host driver --------------------------------
extern "C" void kernel_launch(void* const* d_in, const int* in_sizes, int n_in,
                              void* d_out, int out_size) {
    (void)in_sizes; (void)n_in; (void)out_size;
    const float* X   = (const float*)d_in[0];
    const int*   dag = (const int*)d_in[1];
    const float* Wk  = (const float*)d_in[2],  *bk  = (const float*)d_in[3];
    const float* Wq  = (const float*)d_in[4],  *bq  = (const float*)d_in[5];
    const float* Wv  = (const float*)d_in[6],  *bv  = (const float*)d_in[7];
    const float* Wp  = (const float*)d_in[8],  *bp  = (const float*)d_in[9];
    const float* W1  = (const float*)d_in[10], *b1  = (const float*)d_in[11];
    const float* W2  = (const float*)d_in[12], *b2  = (const float*)d_in[13];
    const float* Wlm = (const float*)d_in[14], *blm = (const float*)d_in[15];
    float* out = (float*)d_out;

    void* pv;
    cudaGetSymbolAddress(&pv, g_Wpack); float* Wpack = (float*)pv;
    cudaGetSymbolAddress(&pv, g_Bias);  float* Bias  = (float*)pv;
    cudaGetSymbolAddress(&pv, g_Amask); unsigned char* Amask = (unsigned char*)pv;
    cudaGetSymbolAddress(&pv, g_Qn);    float* Qn = (float*)pv;
    cudaGetSymbolAddress(&pv, g_Kn);    float* Kn = (float*)pv;
    cudaGetSymbolAddress(&pv, g_Vn);    float* Vn = (float*)pv;
    cudaGetSymbolAddress(&pv, g_AQ);    float* AQ = (float*)pv;
    cudaGetSymbolAddress(&pv, g_AV);    float* AV = (float*)pv;
    cudaGetSymbolAddress(&pv, g_Tb);    float* Tb = (float*)pv;
    cudaGetSymbolAddress(&pv, g_Ob);    float* Ob = (float*)pv;
    cudaGetSymbolAddress(&pv, g_Mha);   float* Mha = (float*)pv;
    cudaGetSymbolAddress(&pv, g_Ff);    float* Ff  = (float*)pv;
    cudaGetSymbolAddress(&pv, g_Xb);    float* Xb  = (float*)pv;

    pack_w_k<<<6144, 256>>>(Wk, Wq, Wv, bk, bq, bv);
    mask_k<<<2048, 256>>>(dag);

    for (int l = 0; l < 4; l++) {
        const unsigned char* Am = Amask + (l ? 262144 : 0);
        {   // QKV projection + bias + swish, scattered to n-major K/Q/V
            GemmParams p; p.A = (l == 0) ? (const void*)X : (const void*)Xb; p.lda = 256;
            p.B = Wpack + (size_t)l * 256 * 1536; p.ldb = 1536;
            p.bias = Bias + l * 1536; p.dst0 = Kn; p.dst1 = Qn; p.dst2 = Vn; p.K = 256;
            gemm_k<128, 128, 8, false, false, 1><<<dim3(12, 64, 1), 256>>>(p);
        }
        {   // AQ = A @ Qn ; AV = A @ Vn   (512 x 8192, K = 512, A is u8 mask)
            GemmParams p; p.A = Am; p.lda = 512; p.B = Qn; p.ldb = 8192;
            p.C = AQ; p.ldc = 8192; p.K = 512;
            gemm_k<128, 128, 8, false, true, 0><<<dim3(64, 4, 1), 256>>>(p);
            p.B = Vn; p.C = AV;
            gemm_k<128, 128, 8, false, true, 0><<<dim3(64, 4, 1), 256>>>(p);
        }
        {   // scores T = (AQ Kt)/8, masked -> Tb  (batched over 128 bh)
            GemmParams p; p.A = AQ; p.lda = 8192; p.sAz = 64;
            p.B = Kn; p.ldb = 8192; p.sBz = 64;
            p.C = Tb; p.ldc = 512; p.sCz = 262144; p.mask = Am; p.K = 64;
            gemm_k<128, 128, 8, true, false, 2><<<dim3(4, 4, 128), 256>>>(p);
        }
        softmax_k<<<8192, 256>>>(Tb);
        {   // O = P @ V + AV, scattered to (b,n) x (h,hs)
            GemmParams p; p.A = Tb; p.lda = 512; p.sAz = 262144;
            p.B = Vn; p.ldb = 8192; p.sBz = 64;
            p.C = Ob; p.res = AV; p.K = 512;
            gemm_k<128, 64, 8, false, false, 3><<<dim3(1, 4, 128), 256>>>(p);
        }
        {   // mha = swish(O @ Wp + bp)
            GemmParams p; p.A = Ob; p.lda = 512;
            p.B = Wp + (size_t)l * 512 * 256; p.ldb = 256; p.bias = bp + l * 256;
            p.C = Mha; p.ldc = 256; p.K = 512;
            gemm_k<128, 128, 8, false, false, 4><<<dim3(2, 64, 1), 256>>>(p);
        }
        {   // ff hidden = swish(mha @ W1 + b1)
            GemmParams p; p.A = Mha; p.lda = 256;
            p.B = W1 + (size_t)l * 256 * 1024; p.ldb = 1024; p.bias = b1 + l * 1024;
            p.C = Ff; p.ldc = 1024; p.K = 256;
            gemm_k<128, 128, 8, false, false, 4><<<dim3(8, 64, 1), 256>>>(p);
        }
        {   // X = ff @ W2 + b2 + mha
            GemmParams p; p.A = Ff; p.lda = 1024;
            p.B = W2 + (size_t)l * 1024 * 256; p.ldb = 256; p.bias = b2 + l * 256;
            p.res = Mha; p.C = Xb; p.ldc = 256; p.K = 1024;
            gemm_k<128, 128, 8, false, false, 5><<<dim3(2, 64, 1), 256>>>(p);
        }
    }
    {   // lm head
        GemmParams p; p.A = Xb; p.lda = 256; p.B = Wlm; p.ldb = 256;
        p.bias = blm; p.C = out; p.ldc = 256; p.K = 256;
        gemm_k<128, 128, 8, false, false, 6><<<dim3(2, 64, 1), 256>>>(p);
    }
}